// round 3
// baseline (speedup 1.0000x reference)
#include <cuda_runtime.h>

// Sparse-conv ResNet block, fp32 baseline.
// y0 = relu(scatter(gather(x) @ W0) + b0)
// out = scatter(gather(y0) @ W1) + b1 + x

constexpr int NPTS   = 100000;
constexpr int NPAIRS = 50000;
constexpr int KOFF   = 27;
constexpr int C      = 128;
constexpr int TILE_P = 64;
constexpr int ASTRIDE = C + 4;   // padded A stride to dodge bank conflicts

// scratch for intermediate activations (51.2 MB) — device global, no allocs
__device__ float g_h[(size_t)NPTS * C];

__global__ void init_h_kernel(const float* __restrict__ b0) {
    int i = blockIdx.x * blockDim.x + threadIdx.x;
    if (i < NPTS * C) g_h[i] = b0[i & (C - 1)];
}

__global__ void relu_h_kernel() {
    int i = blockIdx.x * blockDim.x + threadIdx.x;
    if (i < NPTS * C) g_h[i] = fmaxf(g_h[i], 0.0f);
}

__global__ void init_out_kernel(const float* __restrict__ feat,
                                const float* __restrict__ b1,
                                float* __restrict__ out) {
    int i = blockIdx.x * blockDim.x + threadIdx.x;
    if (i < NPTS * C) out[i] = feat[i] + b1[i & (C - 1)];
}

__device__ __forceinline__ void red_add_v4(float* addr, float a, float b, float c, float d) {
    asm volatile("red.global.add.v4.f32 [%0], {%1,%2,%3,%4};"
                 :: "l"(addr), "f"(a), "f"(b), "f"(c), "f"(d) : "memory");
}

// One block = one kernel offset k + TILE_P gathered rows.
// smem: W[k] 128x128 f32 (64KB) + A tile 64x132 f32 (33KB)
__global__ __launch_bounds__(256, 2)
void spconv_gemm_kernel(const float* __restrict__ X,
                        const float* __restrict__ W,
                        const int* __restrict__ in_map,
                        const int* __restrict__ out_map,
                        float* __restrict__ Y) {
    extern __shared__ float smem[];
    float* Ws = smem;            // [C][C], row = input channel, col = output channel
    float* As = smem + C * C;    // [TILE_P][ASTRIDE]

    const int k   = blockIdx.y;
    const int p0  = blockIdx.x * TILE_P;
    const int tid = threadIdx.x;

    // ---- stage W[k] into smem (float4, fully coalesced; L2-resident) ----
    {
        const float4* Wg  = reinterpret_cast<const float4*>(W + (size_t)k * C * C);
        float4*       Wsm = reinterpret_cast<float4*>(Ws);
        #pragma unroll
        for (int i = 0; i < (C * C / 4) / 256; i++)      // 16 float4 per thread
            Wsm[tid + i * 256] = Wg[tid + i * 256];
    }

    // ---- gather A tile: 4 threads per row, 8 float4 each (rows are contiguous 512B) ----
    {
        const int row  = tid >> 2;
        const int lane = tid & 3;
        int p  = p0 + row;
        int pv = p < NPAIRS ? p : NPAIRS - 1;            // clamp; invalid rows never scattered
        int src = in_map[k * NPAIRS + pv];
        const float4* xr = reinterpret_cast<const float4*>(X + (size_t)src * C);
        float4*       ar = reinterpret_cast<float4*>(As + row * ASTRIDE);
        #pragma unroll
        for (int j = 0; j < 8; j++)
            ar[lane * 8 + j] = xr[lane * 8 + j];
    }
    __syncthreads();

    // ---- 64x128 output tile, 16x16 threads, 4x8 register tile per thread ----
    const int tx = tid & 15;     // output-channel group (8 cols)
    const int ty = tid >> 4;     // pair-row group (4 rows)

    float acc[4][8];
    #pragma unroll
    for (int i = 0; i < 4; i++)
        #pragma unroll
        for (int j = 0; j < 8; j++) acc[i][j] = 0.0f;

    const float* a_base = As + (ty * 4) * ASTRIDE;
    const float* w_base = Ws + tx * 8;

    #pragma unroll 8
    for (int kk = 0; kk < C; kk++) {
        float a0 = a_base[0 * ASTRIDE + kk];
        float a1 = a_base[1 * ASTRIDE + kk];
        float a2 = a_base[2 * ASTRIDE + kk];
        float a3 = a_base[3 * ASTRIDE + kk];
        float4 w0 = *reinterpret_cast<const float4*>(w_base + kk * C);
        float4 w1 = *reinterpret_cast<const float4*>(w_base + kk * C + 4);

        acc[0][0] += a0 * w0.x; acc[0][1] += a0 * w0.y; acc[0][2] += a0 * w0.z; acc[0][3] += a0 * w0.w;
        acc[0][4] += a0 * w1.x; acc[0][5] += a0 * w1.y; acc[0][6] += a0 * w1.z; acc[0][7] += a0 * w1.w;
        acc[1][0] += a1 * w0.x; acc[1][1] += a1 * w0.y; acc[1][2] += a1 * w0.z; acc[1][3] += a1 * w0.w;
        acc[1][4] += a1 * w1.x; acc[1][5] += a1 * w1.y; acc[1][6] += a1 * w1.z; acc[1][7] += a1 * w1.w;
        acc[2][0] += a2 * w0.x; acc[2][1] += a2 * w0.y; acc[2][2] += a2 * w0.z; acc[2][3] += a2 * w0.w;
        acc[2][4] += a2 * w1.x; acc[2][5] += a2 * w1.y; acc[2][6] += a2 * w1.z; acc[2][7] += a2 * w1.w;
        acc[3][0] += a3 * w0.x; acc[3][1] += a3 * w0.y; acc[3][2] += a3 * w0.z; acc[3][3] += a3 * w0.w;
        acc[3][4] += a3 * w1.x; acc[3][5] += a3 * w1.y; acc[3][6] += a3 * w1.z; acc[3][7] += a3 * w1.w;
    }

    // ---- scatter-add: 2 x red.v4 per output row ----
    #pragma unroll
    for (int i = 0; i < 4; i++) {
        int p = p0 + ty * 4 + i;
        if (p < NPAIRS) {
            int dst = out_map[k * NPAIRS + p];
            float* yb = Y + (size_t)dst * C + tx * 8;
            red_add_v4(yb,     acc[i][0], acc[i][1], acc[i][2], acc[i][3]);
            red_add_v4(yb + 4, acc[i][4], acc[i][5], acc[i][6], acc[i][7]);
        }
    }
}

extern "C" void kernel_launch(void* const* d_in, const int* in_sizes, int n_in,
                              void* d_out, int out_size) {
    const float* feat    = (const float*)d_in[0];
    const int*   in_map  = (const int*)  d_in[1];
    const int*   out_map = (const int*)  d_in[2];
    const float* W0      = (const float*)d_in[3];
    const float* b0      = (const float*)d_in[4];
    const float* W1      = (const float*)d_in[5];
    const float* b1      = (const float*)d_in[6];
    float*       out     = (float*)d_out;

    float* h = nullptr;
    cudaGetSymbolAddress((void**)&h, g_h);   // pure query, capture-safe

    const int smem_bytes = (C * C + TILE_P * ASTRIDE) * (int)sizeof(float);  // ~97 KB
    cudaFuncSetAttribute(spconv_gemm_kernel,
                         cudaFuncAttributeMaxDynamicSharedMemorySize, smem_bytes);

    const int n_elems = NPTS * C;
    const int eblocks = (n_elems + 255) / 256;
    dim3 ggrid((NPAIRS + TILE_P - 1) / TILE_P, KOFF);

    // conv0: h = b0; h += scatter(gather(x) @ W0); h = relu(h)
    init_h_kernel<<<eblocks, 256>>>(b0);
    spconv_gemm_kernel<<<ggrid, 256, smem_bytes>>>(feat, W0, in_map, out_map, h);
    relu_h_kernel<<<eblocks, 256>>>();

    // conv1: out = x + b1; out += scatter(gather(h) @ W1)
    init_out_kernel<<<eblocks, 256>>>(feat, b1, out);
    spconv_gemm_kernel<<<ggrid, 256, smem_bytes>>>(h, W1, in_map, out_map, out);
}

// round 8
// speedup vs baseline: 3.5992x; 3.5992x over previous
#include <cuda_runtime.h>
#include <cstdint>

#define DINLINE __device__ __forceinline__

constexpr int NPTS   = 100000;
constexpr int NPAIRS = 50000;
constexpr int KOFF   = 27;
constexpr int C      = 128;
constexpr int TILE_M = 128;
constexpr int GX     = 10;                                // CTAs per offset: 270 total = 1 wave @ 2/SM
constexpr int NTILES = (NPAIRS + TILE_M - 1) / TILE_M;    // 391
constexpr int THREADS = 256;
constexpr int ASTR   = 132;                               // padded row stride (floats): conflict-free LDS.128

// scratch: intermediate activations + pre-transposed tf32 weights
__device__ float g_h[(size_t)NPTS * C];
__device__ float g_Wt[(size_t)2 * KOFF * C * C];          // [conv][k][n][c], tf32-rounded

// ---------------------------------------------------------------- helpers
DINLINE uint32_t cvt_tf32(float f) {
    uint32_t r; asm("cvt.rna.tf32.f32 %0, %1;" : "=r"(r) : "f"(f)); return r;
}
DINLINE void red_add_v2(float* a, float x, float y) {
    asm volatile("red.global.add.v2.f32 [%0], {%1,%2};"
                 :: "l"(a), "f"(x), "f"(y) : "memory");
}
// m16n8k8 tf32 mma: A row-major frag {a0..a3}, B col-major frag {b0,b1}, fp32 acc
DINLINE void mma_tf32(float c[4], uint32_t a0, uint32_t a1, uint32_t a2, uint32_t a3,
                      uint32_t b0, uint32_t b1) {
    asm volatile(
        "mma.sync.aligned.m16n8k8.row.col.f32.tf32.tf32.f32 "
        "{%0,%1,%2,%3}, {%4,%5,%6,%7}, {%8,%9}, {%0,%1,%2,%3};"
        : "+f"(c[0]), "+f"(c[1]), "+f"(c[2]), "+f"(c[3])
        : "r"(a0), "r"(a1), "r"(a2), "r"(a3), "r"(b0), "r"(b1));
}

// Gather 128 rows into smem, tf32-rounded, with a 4x4 transpose permutation inside
// each 16-col group: permuted pos 16kp + 4*(o%4) + (o>>2) for original col o in [0,16).
// Result: one LDS.128 at (row, 16kp + 4*tig) yields {a0,a2} for k-steps 2kp and 2kp+1.
DINLINE void gather_tile(float* As, const float* __restrict__ X,
                         const int* __restrict__ im, int p0, int do_relu, int tid) {
    int r = tid >> 1, half = tid & 1;
    int p  = p0 + r;
    int pv = p < NPAIRS ? p : NPAIRS - 1;        // clamp; invalid rows never scattered
    int src = im[pv];
    const float4* xr = reinterpret_cast<const float4*>(X + (size_t)src * C);
    float* arow = As + r * ASTR;
    #pragma unroll
    for (int j = 0; j < 4; j++) {
        int kp = half * 4 + j;                   // 16-col group index (0..7)
        float4 x0 = xr[kp * 4 + 0], x1 = xr[kp * 4 + 1];
        float4 x2 = xr[kp * 4 + 2], x3 = xr[kp * 4 + 3];
        if (do_relu) {
            x0.x=fmaxf(x0.x,0.f); x0.y=fmaxf(x0.y,0.f); x0.z=fmaxf(x0.z,0.f); x0.w=fmaxf(x0.w,0.f);
            x1.x=fmaxf(x1.x,0.f); x1.y=fmaxf(x1.y,0.f); x1.z=fmaxf(x1.z,0.f); x1.w=fmaxf(x1.w,0.f);
            x2.x=fmaxf(x2.x,0.f); x2.y=fmaxf(x2.y,0.f); x2.z=fmaxf(x2.z,0.f); x2.w=fmaxf(x2.w,0.f);
            x3.x=fmaxf(x3.x,0.f); x3.y=fmaxf(x3.y,0.f); x3.z=fmaxf(x3.z,0.f); x3.w=fmaxf(x3.w,0.f);
        }
        uint4 o0 = { cvt_tf32(x0.x), cvt_tf32(x1.x), cvt_tf32(x2.x), cvt_tf32(x3.x) };
        uint4 o1 = { cvt_tf32(x0.y), cvt_tf32(x1.y), cvt_tf32(x2.y), cvt_tf32(x3.y) };
        uint4 o2 = { cvt_tf32(x0.z), cvt_tf32(x1.z), cvt_tf32(x2.z), cvt_tf32(x3.z) };
        uint4 o3 = { cvt_tf32(x0.w), cvt_tf32(x1.w), cvt_tf32(x2.w), cvt_tf32(x3.w) };
        *reinterpret_cast<uint4*>(arow + kp * 16 +  0) = o0;
        *reinterpret_cast<uint4*>(arow + kp * 16 +  4) = o1;
        *reinterpret_cast<uint4*>(arow + kp * 16 +  8) = o2;
        *reinterpret_cast<uint4*>(arow + kp * 16 + 12) = o3;
    }
}

// ---------------------------------------------------------------- main kernel
// One CTA = one kernel offset k; persistent over P-tiles t = bx, bx+GX, ...
// 8 warps: warp w owns output cols [16w, 16w+16); its B fragments (W[k]^T slice)
// stay in registers for the whole kernel. A comes from smem per tile.
__global__ void __launch_bounds__(THREADS, 2)
spconv_mma_kernel(const float* __restrict__ X,
                  const float* __restrict__ Wt,     // [KOFF][n][c], tf32-rounded
                  const int* __restrict__ in_map,
                  const int* __restrict__ out_map,
                  float* __restrict__ Y,
                  int do_relu)
{
    extern __shared__ float As[];                  // [128][ASTR]
    const int tid = threadIdx.x;
    const int wid = tid >> 5, lid = tid & 31;
    const int g = lid >> 2, tig = lid & 3;         // groupID / thread-in-group
    const int k = blockIdx.y;
    const int* im = in_map  + k * NPAIRS;
    const int* om = out_map + k * NPAIRS;
    const int n0 = wid * 16;

    // ---- load B fragments once: b[ks][nb][i] = Wt[k][n0+8nb+g][8ks+tig+4i] ----
    uint32_t bfr[16][2][2];
    {
        const float* wk = Wt + (size_t)k * C * C;
        #pragma unroll
        for (int ks = 0; ks < 16; ks++)
            #pragma unroll
            for (int nb = 0; nb < 2; nb++) {
                const float* wrow = wk + (n0 + 8 * nb + g) * C + 8 * ks + tig;
                bfr[ks][nb][0] = __float_as_uint(wrow[0]);
                bfr[ks][nb][1] = __float_as_uint(wrow[4]);
            }
    }

    for (int t = blockIdx.x; t < NTILES; t += GX) {
        __syncthreads();                           // prev tile's reads done
        gather_tile(As, X, im, t * TILE_M, do_relu, tid);
        __syncthreads();

        #pragma unroll 1
        for (int mb = 0; mb < 8; mb++) {
            float acc[2][4] = {{0.f,0.f,0.f,0.f},{0.f,0.f,0.f,0.f}};
            const float* a_lo = As + (mb * 16 + g    ) * ASTR;
            const float* a_hi = As + (mb * 16 + g + 8) * ASTR;
            #pragma unroll
            for (int kp = 0; kp < 8; kp++) {
                uint4 lo = *reinterpret_cast<const uint4*>(a_lo + kp * 16 + 4 * tig);
                uint4 hi = *reinterpret_cast<const uint4*>(a_hi + kp * 16 + 4 * tig);
                // k-step 2kp:   A frags (lo.x,hi.x,lo.y,hi.y)
                mma_tf32(acc[0], lo.x, hi.x, lo.y, hi.y, bfr[2*kp  ][0][0], bfr[2*kp  ][0][1]);
                mma_tf32(acc[1], lo.x, hi.x, lo.y, hi.y, bfr[2*kp  ][1][0], bfr[2*kp  ][1][1]);
                // k-step 2kp+1: A frags (lo.z,hi.z,lo.w,hi.w)
                mma_tf32(acc[0], lo.z, hi.z, lo.w, hi.w, bfr[2*kp+1][0][0], bfr[2*kp+1][0][1]);
                mma_tf32(acc[1], lo.z, hi.z, lo.w, hi.w, bfr[2*kp+1][1][0], bfr[2*kp+1][1][1]);
            }
            // scatter: c0,c1 -> row g; c2,c3 -> row g+8; cols n0+8nb+2tig+{0,1}
            int p_lo = t * TILE_M + mb * 16 + g;
            int p_hi = p_lo + 8;
            if (p_lo < NPAIRS) {
                float* y = Y + (size_t)om[p_lo] * C + n0 + 2 * tig;
                red_add_v2(y,     acc[0][0], acc[0][1]);
                red_add_v2(y + 8, acc[1][0], acc[1][1]);
            }
            if (p_hi < NPAIRS) {
                float* y = Y + (size_t)om[p_hi] * C + n0 + 2 * tig;
                red_add_v2(y,     acc[0][2], acc[0][3]);
                red_add_v2(y + 8, acc[1][2], acc[1][3]);
            }
        }
    }
}

// ---------------------------------------------------------------- small kernels
__global__ void wt_kernel(const float* __restrict__ W0, const float* __restrict__ W1) {
    int i = blockIdx.x * blockDim.x + threadIdx.x;       // over KOFF*C*C, layout [k][n][c]
    if (i >= KOFF * C * C) return;
    int k = i / (C * C);
    int rem = i % (C * C);
    int n = rem / C, c = rem % C;
    g_Wt[i] = __uint_as_float(cvt_tf32(W0[(size_t)k * C * C + c * C + n]));
    g_Wt[(size_t)KOFF * C * C + i] =
        __uint_as_float(cvt_tf32(W1[(size_t)k * C * C + c * C + n]));
}

__global__ void init_h_kernel(const float* __restrict__ b0) {
    int i = blockIdx.x * blockDim.x + threadIdx.x;       // float4 index
    if (i < NPTS * C / 4)
        reinterpret_cast<float4*>(g_h)[i] =
            reinterpret_cast<const float4*>(b0)[i & (C / 4 - 1)];
}

__global__ void init_out_kernel(const float* __restrict__ feat,
                                const float* __restrict__ b1,
                                float* __restrict__ out) {
    int i = blockIdx.x * blockDim.x + threadIdx.x;
    if (i < NPTS * C / 4) {
        float4 f = reinterpret_cast<const float4*>(feat)[i];
        float4 b = reinterpret_cast<const float4*>(b1)[i & (C / 4 - 1)];
        f.x += b.x; f.y += b.y; f.z += b.z; f.w += b.w;
        reinterpret_cast<float4*>(out)[i] = f;
    }
}

// ---------------------------------------------------------------- launch
extern "C" void kernel_launch(void* const* d_in, const int* in_sizes, int n_in,
                              void* d_out, int out_size) {
    const float* feat    = (const float*)d_in[0];
    const int*   in_map  = (const int*)  d_in[1];
    const int*   out_map = (const int*)  d_in[2];
    const float* W0      = (const float*)d_in[3];
    const float* b0      = (const float*)d_in[4];
    const float* W1      = (const float*)d_in[5];
    const float* b1      = (const float*)d_in[6];
    float*       out     = (float*)d_out;

    float* h  = nullptr; cudaGetSymbolAddress((void**)&h,  g_h);
    float* wt = nullptr; cudaGetSymbolAddress((void**)&wt, g_Wt);

    const int smem_bytes = TILE_M * ASTR * (int)sizeof(float);   // 67584
    cudaFuncSetAttribute(spconv_mma_kernel,
                         cudaFuncAttributeMaxDynamicSharedMemorySize, smem_bytes);

    const int nv4 = NPTS * C / 4;
    dim3 ggrid(GX, KOFF);

    wt_kernel<<<(KOFF * C * C + 255) / 256, 256>>>(W0, W1);

    // conv0: h = b0; h += scatter(gather(x) @ W0)   (relu deferred into conv1's gather)
    init_h_kernel<<<(nv4 + 255) / 256, 256>>>(b0);
    spconv_mma_kernel<<<ggrid, THREADS, smem_bytes>>>(feat, wt, in_map, out_map, h, 0);

    // conv1: out = x + b1; out += scatter(gather(relu(h)) @ W1)
    init_out_kernel<<<(nv4 + 255) / 256, 256>>>(feat, b1, out);
    spconv_mma_kernel<<<ggrid, THREADS, smem_bytes>>>(h, wt + (size_t)KOFF * C * C,
                                                     in_map, out_map, out, 1);
}